// round 13
// baseline (speedup 1.0000x reference)
#include <cuda_runtime.h>
#include <cuda.h>
#include <cstdint>

#define NTPL 10
#define NACC 11                                   // 10 cross + 1 x·x
#define PIX 784
#define IMG_BYTES 3136                            // PIX*4
#define TILE 128                                  // images per tile
#define NGRP 4                                    // 4 groups of 32 images
#define CHUNKS 196
#define SCH 7                                     // chunks per stage
#define NSTG 28                                   // stages per tile
#define NBUF 12                                   // smem buffers
#define NW 16
#define THREADS (NW * 32)                         // 512
#define SROW 112                                  // bytes per image row per stage (28 floats)
#define BUF_BYTES (TILE * SROW)                   // 14336
#define TM_OFF (NBUF * BUF_BYTES)                 // 172032 templates [k][chunk] 16B
#define MB_OFF (TM_OFF + NTPL * PIX * 4)          // 203392: 12 mbarriers, 16B stride
#define TSQ_OFF (MB_OFF + NBUF * 16)              // 203584: 10 doubles
#define SMEM_TOTAL (TSQ_OFF + 96)                 // 203680 <= 232448

// Epilogue scratch lives in buffers 5..11 (71680..172032)
#define RED_OFF (5 * BUF_BYTES)                   // 71680, size 11*16*128*4 = 90112
#define XXD_OFF (RED_OFF + 90112)                 // 161792, 128 doubles
#define DF_OFF (XXD_OFF + 1024)                   // 162816, 10*128 floats -> 167936 <= 172032

#define FMA2(acc, a, b) \
    asm("fma.rn.f32x2 %0, %1, %2, %0;" : "+l"(acc) : "l"(a), "l"(b))

#define XLOAD(g, OFF) \
    asm("ld.shared.v2.u64 {%0, %1}, [%2+" OFF "];" \
        : "=l"(x01[g]), "=l"(x23[g]) : "r"(xb))

#define KSTEP(k, OFF) do { \
    uint64_t a01, a23; \
    asm("ld.shared.v2.u64 {%0, %1}, [%2+" OFF "];" \
        : "=l"(a01), "=l"(a23) : "r"(tb)); \
    FMA2(acc[k][0], x01[0], a01); FMA2(acc[k][0], x23[0], a23); \
    FMA2(acc[k][1], x01[1], a01); FMA2(acc[k][1], x23[1], a23); \
    FMA2(acc[k][2], x01[2], a01); FMA2(acc[k][2], x23[2], a23); \
    FMA2(acc[k][3], x01[3], a01); FMA2(acc[k][3], x23[3], a23); \
} while (0)

__device__ __forceinline__ void mbar_wait(uint32_t addr, uint32_t phase) {
    uint32_t done = 0;
    while (!done) {
        asm volatile(
            "{\n\t.reg .pred p;\n\t"
            "mbarrier.try_wait.parity.acquire.cta.shared::cta.b64 p, [%1], %2, 0x989680;\n\t"
            "selp.b32 %0, 1, 0, p;\n\t}"
            : "=r"(done) : "r"(addr), "r"(phase) : "memory");
    }
}

// One thread: fetch stage s (28 floats x 128 rows) of a tile with one 2D TMA.
__device__ __forceinline__ void fetch_stage(const CUtensorMap* tmap, int tile, int s,
                                            uint32_t smb) {
    const int b = s % NBUF;
    const uint32_t mbar = smb + MB_OFF + (uint32_t)(b * 16);
    asm volatile("mbarrier.arrive.expect_tx.shared.b64 _, [%0], %1;"
                 :: "r"(mbar), "r"((uint32_t)BUF_BYTES) : "memory");
    asm volatile(
        "cp.async.bulk.tensor.2d.shared::cta.global.tile.mbarrier::complete_tx::bytes "
        "[%0], [%1, {%2, %3}], [%4];"
        :: "r"(smb + (uint32_t)(b * BUF_BYTES)), "l"(tmap),
           "r"(s * (SCH * 4)), "r"(tile * TILE), "r"(mbar) : "memory");
}

__global__ void __launch_bounds__(THREADS, 1)
mse_argmin_kernel(const __grid_constant__ CUtensorMap tmap,
                  const float* __restrict__ tg, float* __restrict__ out, int ntiles) {
    extern __shared__ float sm[];
    const uint32_t smb = (uint32_t)__cvta_generic_to_shared(sm);
    const int tid = threadIdx.x;
    const int w = tid >> 5;
    const int lane = tid & 31;
    const int G = gridDim.x;
    const int t0 = blockIdx.x;
    const double INV784 = 1.0 / 784.0;

    if (tid == 0) {
        asm volatile("prefetch.tensormap [%0];" :: "l"(&tmap));
        #pragma unroll
        for (int b = 0; b < NBUF; b++)
            asm volatile("mbarrier.init.shared.b64 [%0], 1;"
                         :: "r"(smb + MB_OFF + (uint32_t)(b * 16)) : "memory");
        asm volatile("fence.proxy.async;" ::: "memory");
    }
    __syncthreads();

    // Templates -> smem [k][chunk] 16B granules (overlaps with prime fetches).
    {
        const float4* tg4 = (const float4*)tg;
        float4* tm4 = (float4*)(sm + (TM_OFF >> 2));
        for (int i = tid; i < NTPL * CHUNKS; i += THREADS) tm4[i] = tg4[i];
    }
    // Exact (fp64) squared template norms (one warp per template).
    double* tsq_d = (double*)((char*)sm + TSQ_OFF);
    if (w < NTPL) {
        const float* tp = tg + w * PIX;
        double a = 0.0;
        for (int p = lane; p < PIX; p += 32) a = fma((double)tp[p], (double)tp[p], a);
        #pragma unroll
        for (int s = 16; s > 0; s >>= 1) a += __shfl_xor_sync(0xffffffffu, a, s);
        if (lane == 0) tsq_d[w] = a;
    }
    __syncthreads();

    uint32_t pmask = 0;                           // per-buffer expected parity bits
    int firsttile = 1;

    for (int ti = t0; ti < ntiles; ti += G) {
        // Prime: first tile issues stages 0..10; later tiles issued 0..4 during
        // the previous epilogue, so publish scratch to async proxy + issue 5..10.
        if (tid == 0) {
            if (firsttile) {
                for (int s = 0; s <= 10; s++) fetch_stage(&tmap, ti, s, smb);
            } else {
                asm volatile("fence.proxy.async;" ::: "memory");
                for (int s = 5; s <= 10; s++) fetch_stage(&tmap, ti, s, smb);
            }
        }
        firsttile = 0;

        uint64_t acc[NACC][NGRP];
        #pragma unroll
        for (int k = 0; k < NACC; k++)
            #pragma unroll
            for (int g = 0; g < NGRP; g++) acc[k][g] = 0ull;

        // Warp w owns chunks c == w (mod 16), increasing c: in stage s the
        // owned chunk (if any) is local index r = (w - 7s) mod 16, r < 7.
        int r = w;
        int b = 0;
        uint32_t tcb = smb + TM_OFF;              // stage base in template array
        for (int s = 0; s < NSTG; s++) {
            mbar_wait(smb + MB_OFF + (uint32_t)(b * 16), (pmask >> b) & 1u);
            pmask ^= (1u << b);

            if (r < SCH) {
                const uint32_t xb = smb + (uint32_t)(b * BUF_BYTES)
                                  + (uint32_t)(lane * SROW) + (uint32_t)(r * 16);
                const uint32_t tb = tcb + (uint32_t)(r * 16);
                uint64_t x01[NGRP], x23[NGRP];
                XLOAD(0, "0"); XLOAD(1, "3584"); XLOAD(2, "7168"); XLOAD(3, "10752");
                KSTEP(0, "0");     KSTEP(1, "3136");  KSTEP(2, "6272");
                KSTEP(3, "9408");  KSTEP(4, "12544"); KSTEP(5, "15680");
                KSTEP(6, "18816"); KSTEP(7, "21952"); KSTEP(8, "25088");
                KSTEP(9, "28224");
                FMA2(acc[NTPL][0], x01[0], x01[0]); FMA2(acc[NTPL][0], x23[0], x23[0]);
                FMA2(acc[NTPL][1], x01[1], x01[1]); FMA2(acc[NTPL][1], x23[1], x23[1]);
                FMA2(acc[NTPL][2], x01[2], x01[2]); FMA2(acc[NTPL][2], x23[2], x23[2]);
                FMA2(acc[NTPL][3], x01[3], x01[3]); FMA2(acc[NTPL][3], x23[3], x23[3]);
            }
            __syncthreads();                      // stage consumed by everyone
            if (tid == 0 && s + 11 < NSTG) fetch_stage(&tmap, ti, s + 11, smb);
            r = (r + 9) & 15;
            tcb += SROW;
            if (++b == NBUF) b = 0;
        }

        // Overlap the tile-boundary drain: prefetch next tile's stages 0..4
        // into buffers 0..4 (epilogue scratch is buffers 5..11 only).
        if (tid == 0 && ti + G < ntiles)
            for (int s = 0; s <= 4; s++) fetch_stage(&tmap, ti + G, s, smb);

        // ---- epilogue (identical arithmetic to R9) ----
        float* red = (float*)((char*)sm + RED_OFF);            // [k][w][img]
        #pragma unroll
        for (int k = 0; k < NACC; k++)
            #pragma unroll
            for (int g = 0; g < NGRP; g++) {
                uint32_t lo, hi;
                asm("mov.b64 {%0, %1}, %2;" : "=r"(lo), "=r"(hi) : "l"(acc[k][g]));
                red[(k * NW + w) * TILE + g * 32 + lane] =
                    __uint_as_float(lo) + __uint_as_float(hi);
            }
        __syncthreads();

        double* xxd = (double*)((char*)sm + XXD_OFF);          // [img]
        float* df = (float*)((char*)sm + DF_OFF);              // [k][img]

        // Pass A: exact 16-way fold of x·x (k=10) via TwoSum -> fp64.
        if (tid < TILE) {
            const float* rp = red + NTPL * (NW * TILE) + tid;
            float fs = 0.f, fe = 0.f;
            #pragma unroll
            for (int ww = 0; ww < NW; ww++) {
                const float v = rp[ww * TILE];
                const float tt = fs + v;
                const float z = tt - fs;
                fe += (fs - (tt - z)) + (v - z);
                fs = tt;
            }
            xxd[tid] = (double)fs + (double)fe;
        }
        __syncthreads();

        // Pass B: fold k=0..9 and form fp32-rounded distances.
        for (int p = tid; p < NTPL * TILE; p += THREADS) {
            const int k = p >> 7, img = p & (TILE - 1);
            const float* rp = red + k * (NW * TILE) + img;
            float fs = 0.f, fe = 0.f;
            #pragma unroll
            for (int ww = 0; ww < NW; ww++) {
                const float v = rp[ww * TILE];
                const float tt = fs + v;
                const float z = tt - fs;
                fe += (fs - (tt - z)) + (v - z);
                fs = tt;
            }
            const double c = (double)fs + (double)fe;
            df[p] = (float)((fma(-2.0, c, xxd[img]) + tsq_d[k]) * INV784);
        }
        __syncthreads();

        // argmin (strict <, first index wins ties == jnp.argmin).
        if (tid < TILE) {
            float best = df[tid];
            int bi = 0;
            #pragma unroll
            for (int kk = 1; kk < NTPL; kk++) {
                const float v = df[kk * TILE + tid];
                if (v < best) { best = v; bi = kk; }
            }
            out[(size_t)ti * TILE + tid] = (float)bi;
        }
        __syncthreads();                          // scratch dead before refills
    }
}

typedef CUresult (*EncodeFn)(CUtensorMap*, CUtensorMapDataType, cuuint32_t, void*,
                             const cuuint64_t*, const cuuint64_t*, const cuuint32_t*,
                             const cuuint32_t*, CUtensorMapInterleave, CUtensorMapSwizzle,
                             CUtensorMapL2promotion, CUtensorMapFloatOOBfill);

extern "C" void kernel_launch(void* const* d_in, const int* in_sizes, int n_in,
                              void* d_out, int out_size) {
    // Robust to input ordering: x is the big one.
    const float* a = (const float*)d_in[0];
    const float* b = (const float*)d_in[1];
    const float* xg;
    const float* tg;
    long nx;
    if (in_sizes[0] >= in_sizes[1]) { xg = a; tg = b; nx = in_sizes[0]; }
    else                            { xg = b; tg = a; nx = in_sizes[1]; }

    const int B = (int)(nx / PIX);
    const int ntiles = B / TILE;   // 262144/128 = 2048, exact

    // Encode the x tensormap: [784 cols x B rows] fp32, box [28 x 128].
    static CUtensorMap tmap;       // persists across graph replays
    {
        EncodeFn enc = nullptr;
        cudaDriverEntryPointQueryResult qr = cudaDriverEntryPointSuccess;
        cudaError_t e = cudaGetDriverEntryPointByVersion(
            "cuTensorMapEncodeTiled", (void**)&enc, 12000, cudaEnableDefault, &qr);
        if (e != cudaSuccess || qr != cudaDriverEntryPointSuccess || enc == nullptr) {
            enc = nullptr;
            cudaGetDriverEntryPoint("cuTensorMapEncodeTiled", (void**)&enc,
                                    cudaEnableDefault, &qr);
        }
        if (enc != nullptr) {
            cuuint64_t gdims[2] = {(cuuint64_t)PIX, (cuuint64_t)B};
            cuuint64_t gstride[1] = {(cuuint64_t)IMG_BYTES};
            cuuint32_t box[2] = {(cuuint32_t)(SCH * 4), (cuuint32_t)TILE};
            cuuint32_t estride[2] = {1, 1};
            enc(&tmap, CU_TENSOR_MAP_DATA_TYPE_FLOAT32, 2, (void*)xg,
                gdims, gstride, box, estride,
                CU_TENSOR_MAP_INTERLEAVE_NONE, CU_TENSOR_MAP_SWIZZLE_NONE,
                CU_TENSOR_MAP_L2_PROMOTION_L2_128B, CU_TENSOR_MAP_FLOAT_OOB_FILL_NONE);
        }
    }

    int dev = 0;
    cudaGetDevice(&dev);
    int nsm = 148;
    cudaDeviceGetAttribute(&nsm, cudaDevAttrMultiProcessorCount, dev);
    int grid = nsm < ntiles ? nsm : ntiles;

    cudaFuncSetAttribute(mse_argmin_kernel,
                         cudaFuncAttributeMaxDynamicSharedMemorySize, SMEM_TOTAL);

    mse_argmin_kernel<<<grid, THREADS, SMEM_TOTAL>>>(tmap, tg, (float*)d_out, ntiles);
}

// round 14
// speedup vs baseline: 1.0028x; 1.0028x over previous
#include <cuda_runtime.h>
#include <cuda.h>
#include <cstdint>

#define NTPL 10
#define NACC 11                                   // 10 cross + 1 x·x
#define PIX 784
#define IMG_BYTES 3136                            // PIX*4
#define TILE 128                                  // images per tile
#define NGRP 4                                    // 4 groups of 32 images
#define CHUNKS 196
#define SCH 7                                     // chunks per stage
#define NSTG 28                                   // stages per tile
#define NBUF 12                                   // smem buffers
#define NW 16
#define THREADS (NW * 32)                         // 512
#define SROW 112                                  // bytes per image row per stage (28 floats)
#define BUF_BYTES (TILE * SROW)                   // 14336
#define TM_OFF (NBUF * BUF_BYTES)                 // 172032 templates [k][chunk] 16B
#define MB_OFF (TM_OFF + NTPL * PIX * 4)          // 203392: 12 mbarriers, 16B stride
#define TSQ_OFF (MB_OFF + NBUF * 16)              // 203584: 10 doubles
#define SMEM_TOTAL (TSQ_OFF + 96)                 // 203680 <= 232448

// Epilogue scratch lives in buffers 5..11 (71680..172032)
#define RED_OFF (5 * BUF_BYTES)                   // 71680, size 11*16*128*4 = 90112
#define XXD_OFF (RED_OFF + 90112)                 // 161792, 128 doubles
#define DF_OFF (XXD_OFF + 1024)                   // 162816, 10*128 floats -> 167936 <= 172032

#define FMA2(acc, a, b) \
    asm("fma.rn.f32x2 %0, %1, %2, %0;" : "+l"(acc) : "l"(a), "l"(b))

#define XLOAD(g, OFF) \
    asm("ld.shared.v2.u64 {%0, %1}, [%2+" OFF "];" \
        : "=l"(x01[g]), "=l"(x23[g]) : "r"(xb))

#define KSTEP(k, OFF) do { \
    uint64_t a01, a23; \
    asm("ld.shared.v2.u64 {%0, %1}, [%2+" OFF "];" \
        : "=l"(a01), "=l"(a23) : "r"(tb)); \
    FMA2(acc[k][0], x01[0], a01); FMA2(acc[k][0], x23[0], a23); \
    FMA2(acc[k][1], x01[1], a01); FMA2(acc[k][1], x23[1], a23); \
    FMA2(acc[k][2], x01[2], a01); FMA2(acc[k][2], x23[2], a23); \
    FMA2(acc[k][3], x01[3], a01); FMA2(acc[k][3], x23[3], a23); \
} while (0)

__device__ __forceinline__ void mbar_wait(uint32_t addr, uint32_t phase) {
    uint32_t done = 0;
    while (!done) {
        asm volatile(
            "{\n\t.reg .pred p;\n\t"
            "mbarrier.try_wait.parity.acquire.cta.shared::cta.b64 p, [%1], %2, 0x989680;\n\t"
            "selp.b32 %0, 1, 0, p;\n\t}"
            : "=r"(done) : "r"(addr), "r"(phase) : "memory");
    }
}

// One thread: fetch stage s (28 floats x 128 rows) of a tile with one 2D TMA.
__device__ __forceinline__ void fetch_stage(const CUtensorMap* tmap, int tile, int s,
                                            uint32_t smb) {
    const int b = s % NBUF;
    const uint32_t mbar = smb + MB_OFF + (uint32_t)(b * 16);
    asm volatile("mbarrier.arrive.expect_tx.shared.b64 _, [%0], %1;"
                 :: "r"(mbar), "r"((uint32_t)BUF_BYTES) : "memory");
    asm volatile(
        "cp.async.bulk.tensor.2d.shared::cta.global.tile.mbarrier::complete_tx::bytes "
        "[%0], [%1, {%2, %3}], [%4];"
        :: "r"(smb + (uint32_t)(b * BUF_BYTES)), "l"(tmap),
           "r"(s * (SCH * 4)), "r"(tile * TILE), "r"(mbar) : "memory");
}

__global__ void __launch_bounds__(THREADS, 1)
mse_argmin_kernel(const __grid_constant__ CUtensorMap tmap,
                  const float* __restrict__ tg, float* __restrict__ out, int ntiles) {
    extern __shared__ float sm[];
    const uint32_t smb = (uint32_t)__cvta_generic_to_shared(sm);
    const int tid = threadIdx.x;
    const int w = tid >> 5;
    const int lane = tid & 31;
    const int G = gridDim.x;
    const int t0 = blockIdx.x;
    const double INV784 = 1.0 / 784.0;

    if (tid == 0) {
        asm volatile("prefetch.tensormap [%0];" :: "l"(&tmap));
        #pragma unroll
        for (int b = 0; b < NBUF; b++)
            asm volatile("mbarrier.init.shared.b64 [%0], 1;"
                         :: "r"(smb + MB_OFF + (uint32_t)(b * 16)) : "memory");
        asm volatile("fence.proxy.async;" ::: "memory");
    }
    __syncthreads();

    // Templates -> smem [k][chunk] 16B granules (overlaps with prime fetches).
    {
        const float4* tg4 = (const float4*)tg;
        float4* tm4 = (float4*)(sm + (TM_OFF >> 2));
        for (int i = tid; i < NTPL * CHUNKS; i += THREADS) tm4[i] = tg4[i];
    }
    // Exact (fp64) squared template norms (one warp per template).
    double* tsq_d = (double*)((char*)sm + TSQ_OFF);
    if (w < NTPL) {
        const float* tp = tg + w * PIX;
        double a = 0.0;
        for (int p = lane; p < PIX; p += 32) a = fma((double)tp[p], (double)tp[p], a);
        #pragma unroll
        for (int s = 16; s > 0; s >>= 1) a += __shfl_xor_sync(0xffffffffu, a, s);
        if (lane == 0) tsq_d[w] = a;
    }
    __syncthreads();

    uint32_t pmask = 0;                           // per-buffer expected parity bits
    int firsttile = 1;

    for (int ti = t0; ti < ntiles; ti += G) {
        // Prime: first tile issues stages 0..10; later tiles issued 0..4 during
        // the previous epilogue, so publish scratch to async proxy + issue 5..10.
        if (tid == 0) {
            if (firsttile) {
                for (int s = 0; s <= 10; s++) fetch_stage(&tmap, ti, s, smb);
            } else {
                asm volatile("fence.proxy.async;" ::: "memory");
                for (int s = 5; s <= 10; s++) fetch_stage(&tmap, ti, s, smb);
            }
        }
        firsttile = 0;

        uint64_t acc[NACC][NGRP];
        #pragma unroll
        for (int k = 0; k < NACC; k++)
            #pragma unroll
            for (int g = 0; g < NGRP; g++) acc[k][g] = 0ull;

        // Warp w owns chunks c == w (mod 16), increasing c: in stage s the
        // owned chunk (if any) is local index r = (w - 7s) mod 16, r < 7.
        int r = w;
        int b = 0;
        uint32_t tcb = smb + TM_OFF;              // stage base in template array
        for (int s = 0; s < NSTG; s++) {
            mbar_wait(smb + MB_OFF + (uint32_t)(b * 16), (pmask >> b) & 1u);
            pmask ^= (1u << b);

            if (r < SCH) {
                const uint32_t xb = smb + (uint32_t)(b * BUF_BYTES)
                                  + (uint32_t)(lane * SROW) + (uint32_t)(r * 16);
                const uint32_t tb = tcb + (uint32_t)(r * 16);
                uint64_t x01[NGRP], x23[NGRP];
                XLOAD(0, "0"); XLOAD(1, "3584"); XLOAD(2, "7168"); XLOAD(3, "10752");
                KSTEP(0, "0");     KSTEP(1, "3136");  KSTEP(2, "6272");
                KSTEP(3, "9408");  KSTEP(4, "12544"); KSTEP(5, "15680");
                KSTEP(6, "18816"); KSTEP(7, "21952"); KSTEP(8, "25088");
                KSTEP(9, "28224");
                FMA2(acc[NTPL][0], x01[0], x01[0]); FMA2(acc[NTPL][0], x23[0], x23[0]);
                FMA2(acc[NTPL][1], x01[1], x01[1]); FMA2(acc[NTPL][1], x23[1], x23[1]);
                FMA2(acc[NTPL][2], x01[2], x01[2]); FMA2(acc[NTPL][2], x23[2], x23[2]);
                FMA2(acc[NTPL][3], x01[3], x01[3]); FMA2(acc[NTPL][3], x23[3], x23[3]);
            }
            __syncthreads();                      // stage consumed by everyone
            if (tid == 0 && s + 11 < NSTG) fetch_stage(&tmap, ti, s + 11, smb);
            r = (r + 9) & 15;
            tcb += SROW;
            if (++b == NBUF) b = 0;
        }

        // Overlap the tile-boundary drain: prefetch next tile's stages 0..4
        // into buffers 0..4 (epilogue scratch is buffers 5..11 only).
        if (tid == 0 && ti + G < ntiles)
            for (int s = 0; s <= 4; s++) fetch_stage(&tmap, ti + G, s, smb);

        // ---- epilogue (identical arithmetic to R9) ----
        float* red = (float*)((char*)sm + RED_OFF);            // [k][w][img]
        #pragma unroll
        for (int k = 0; k < NACC; k++)
            #pragma unroll
            for (int g = 0; g < NGRP; g++) {
                uint32_t lo, hi;
                asm("mov.b64 {%0, %1}, %2;" : "=r"(lo), "=r"(hi) : "l"(acc[k][g]));
                red[(k * NW + w) * TILE + g * 32 + lane] =
                    __uint_as_float(lo) + __uint_as_float(hi);
            }
        __syncthreads();

        double* xxd = (double*)((char*)sm + XXD_OFF);          // [img]
        float* df = (float*)((char*)sm + DF_OFF);              // [k][img]

        // Pass A: exact 16-way fold of x·x (k=10) via TwoSum -> fp64.
        if (tid < TILE) {
            const float* rp = red + NTPL * (NW * TILE) + tid;
            float fs = 0.f, fe = 0.f;
            #pragma unroll
            for (int ww = 0; ww < NW; ww++) {
                const float v = rp[ww * TILE];
                const float tt = fs + v;
                const float z = tt - fs;
                fe += (fs - (tt - z)) + (v - z);
                fs = tt;
            }
            xxd[tid] = (double)fs + (double)fe;
        }
        __syncthreads();

        // Pass B: fold k=0..9 and form fp32-rounded distances.
        for (int p = tid; p < NTPL * TILE; p += THREADS) {
            const int k = p >> 7, img = p & (TILE - 1);
            const float* rp = red + k * (NW * TILE) + img;
            float fs = 0.f, fe = 0.f;
            #pragma unroll
            for (int ww = 0; ww < NW; ww++) {
                const float v = rp[ww * TILE];
                const float tt = fs + v;
                const float z = tt - fs;
                fe += (fs - (tt - z)) + (v - z);
                fs = tt;
            }
            const double c = (double)fs + (double)fe;
            df[p] = (float)((fma(-2.0, c, xxd[img]) + tsq_d[k]) * INV784);
        }
        __syncthreads();

        // argmin (strict <, first index wins ties == jnp.argmin).
        if (tid < TILE) {
            float best = df[tid];
            int bi = 0;
            #pragma unroll
            for (int kk = 1; kk < NTPL; kk++) {
                const float v = df[kk * TILE + tid];
                if (v < best) { best = v; bi = kk; }
            }
            out[(size_t)ti * TILE + tid] = (float)bi;
        }
        __syncthreads();                          // scratch dead before refills
    }
}

typedef CUresult (*EncodeFn)(CUtensorMap*, CUtensorMapDataType, cuuint32_t, void*,
                             const cuuint64_t*, const cuuint64_t*, const cuuint32_t*,
                             const cuuint32_t*, CUtensorMapInterleave, CUtensorMapSwizzle,
                             CUtensorMapL2promotion, CUtensorMapFloatOOBfill);

extern "C" void kernel_launch(void* const* d_in, const int* in_sizes, int n_in,
                              void* d_out, int out_size) {
    // Robust to input ordering: x is the big one.
    const float* a = (const float*)d_in[0];
    const float* b = (const float*)d_in[1];
    const float* xg;
    const float* tg;
    long nx;
    if (in_sizes[0] >= in_sizes[1]) { xg = a; tg = b; nx = in_sizes[0]; }
    else                            { xg = b; tg = a; nx = in_sizes[1]; }

    const int B = (int)(nx / PIX);
    const int ntiles = B / TILE;   // 262144/128 = 2048, exact

    // Encode the x tensormap: [784 cols x B rows] fp32, box [28 x 128].
    static CUtensorMap tmap;       // persists across graph replays
    {
        EncodeFn enc = nullptr;
        cudaDriverEntryPointQueryResult qr = cudaDriverEntryPointSuccess;
        cudaError_t e = cudaGetDriverEntryPointByVersion(
            "cuTensorMapEncodeTiled", (void**)&enc, 12000, cudaEnableDefault, &qr);
        if (e != cudaSuccess || qr != cudaDriverEntryPointSuccess || enc == nullptr) {
            enc = nullptr;
            cudaGetDriverEntryPoint("cuTensorMapEncodeTiled", (void**)&enc,
                                    cudaEnableDefault, &qr);
        }
        if (enc != nullptr) {
            cuuint64_t gdims[2] = {(cuuint64_t)PIX, (cuuint64_t)B};
            cuuint64_t gstride[1] = {(cuuint64_t)IMG_BYTES};
            cuuint32_t box[2] = {(cuuint32_t)(SCH * 4), (cuuint32_t)TILE};
            cuuint32_t estride[2] = {1, 1};
            enc(&tmap, CU_TENSOR_MAP_DATA_TYPE_FLOAT32, 2, (void*)xg,
                gdims, gstride, box, estride,
                CU_TENSOR_MAP_INTERLEAVE_NONE, CU_TENSOR_MAP_SWIZZLE_NONE,
                CU_TENSOR_MAP_L2_PROMOTION_L2_128B, CU_TENSOR_MAP_FLOAT_OOB_FILL_NONE);
        }
    }

    int dev = 0;
    cudaGetDevice(&dev);
    int nsm = 148;
    cudaDeviceGetAttribute(&nsm, cudaDevAttrMultiProcessorCount, dev);
    int grid = nsm < ntiles ? nsm : ntiles;

    cudaFuncSetAttribute(mse_argmin_kernel,
                         cudaFuncAttributeMaxDynamicSharedMemorySize, SMEM_TOTAL);

    mse_argmin_kernel<<<grid, THREADS, SMEM_TOTAL>>>(tmap, tg, (float*)d_out, ntiles);
}

// round 16
// speedup vs baseline: 1.2346x; 1.2311x over previous
#include <cuda_runtime.h>
#include <cuda.h>
#include <cstdint>

#define NTPL 10
#define NACC 11                                   // 10 cross + 1 x·x
#define PIX 784
#define IMG_BYTES 3136                            // PIX*4
#define TILE 64                                   // images per tile
#define NGRP 2                                    // 2 groups of 32 images
#define CHUNKS 196
#define QCHUNKS 49                                // chunks per quarter
#define NQ 4                                      // quarters per tile
#define NBUF 4                                    // buffer q holds quarter q
#define NW 16
#define THREADS (NW * 32)                         // 512
#define QROW 784                                  // bytes per image row per quarter
#define BUF_BYTES (TILE * QROW)                   // 50176; 196w == 4 mod 32 -> conflict-free
#define TM_OFF (NBUF * BUF_BYTES)                 // 200704 templates [k][chunk] 16B
#define MB_OFF (TM_OFF + NTPL * PIX * 4)          // 232064: 4 mbarriers, 16B stride
#define TSQ_OFF (MB_OFF + 64)                     // 232128: 10 doubles
#define SMEM_TOTAL (TSQ_OFF + 80)                 // 232208 <= 232448

// Epilogue scratch = buffers 2,3 (100352..200704)
#define RED_OFF (2 * BUF_BYTES)                   // 100352, 11*16*64*4 = 45056
#define XXD_OFF (RED_OFF + 45056)                 // 145408, 64 doubles
#define DF_OFF (XXD_OFF + 512)                    // 145920, 10*64 floats -> 148480 ok

#define FMA2(acc, a, b) \
    asm("fma.rn.f32x2 %0, %1, %2, %0;" : "+l"(acc) : "l"(a), "l"(b))

#define XLOAD(g, OFF) \
    asm("ld.shared.v2.u64 {%0, %1}, [%2+" OFF "];" \
        : "=l"(x01[g]), "=l"(x23[g]) : "r"(xb))

#define KSTEP(k, OFF) do { \
    uint64_t a01, a23; \
    asm("ld.shared.v2.u64 {%0, %1}, [%2+" OFF "];" \
        : "=l"(a01), "=l"(a23) : "r"(tb)); \
    FMA2(acc[k][0], x01[0], a01); FMA2(acc[k][0], x23[0], a23); \
    FMA2(acc[k][1], x01[1], a01); FMA2(acc[k][1], x23[1], a23); \
} while (0)

__device__ __forceinline__ void mbar_wait(uint32_t addr, uint32_t phase) {
    uint32_t done = 0;
    while (!done) {
        asm volatile(
            "{\n\t.reg .pred p;\n\t"
            "mbarrier.try_wait.parity.acquire.cta.shared::cta.b64 p, [%1], %2, 0x989680;\n\t"
            "selp.b32 %0, 1, 0, p;\n\t}"
            : "=r"(done) : "r"(addr), "r"(phase) : "memory");
    }
}

// One thread: fetch quarter q of a 64-image tile into buffer q (one 2D TMA).
__device__ __forceinline__ void fetch_q(const CUtensorMap* tmap, int tile, int q,
                                        uint32_t smb) {
    const uint32_t mbar = smb + MB_OFF + (uint32_t)(q * 16);
    asm volatile("mbarrier.arrive.expect_tx.shared.b64 _, [%0], %1;"
                 :: "r"(mbar), "r"((uint32_t)BUF_BYTES) : "memory");
    asm volatile(
        "cp.async.bulk.tensor.2d.shared::cta.global.tile.mbarrier::complete_tx::bytes "
        "[%0], [%1, {%2, %3}], [%4];"
        :: "r"(smb + (uint32_t)(q * BUF_BYTES)), "l"(tmap),
           "r"(q * (QCHUNKS * 4)), "r"(tile * TILE), "r"(mbar) : "memory");
}

__global__ void __launch_bounds__(THREADS, 1)
mse_argmin_kernel(const __grid_constant__ CUtensorMap tmap,
                  const float* __restrict__ tg, float* __restrict__ out, int ntiles) {
    extern __shared__ float sm[];
    const uint32_t smb = (uint32_t)__cvta_generic_to_shared(sm);
    const int tid = threadIdx.x;
    const int w = tid >> 5;
    const int lane = tid & 31;
    const int G = gridDim.x;
    const int t0 = blockIdx.x;
    const double INV784 = 1.0 / 784.0;

    if (tid == 0) {
        asm volatile("prefetch.tensormap [%0];" :: "l"(&tmap));
        #pragma unroll
        for (int b = 0; b < NBUF; b++)
            asm volatile("mbarrier.init.shared.b64 [%0], 1;"
                         :: "r"(smb + MB_OFF + (uint32_t)(b * 16)) : "memory");
        asm volatile("fence.proxy.async;" ::: "memory");
    }
    __syncthreads();

    // Prime: all 4 quarters of the first tile.
    if (tid == 0 && t0 < ntiles) {
        #pragma unroll
        for (int q = 0; q < NQ; q++) fetch_q(&tmap, t0, q, smb);
    }

    // Templates -> smem [k][chunk] 16B granules (overlaps with prime fetches).
    {
        const float4* tg4 = (const float4*)tg;
        float4* tm4 = (float4*)(sm + (TM_OFF >> 2));
        for (int i = tid; i < NTPL * CHUNKS; i += THREADS) tm4[i] = tg4[i];
    }
    // Exact (fp64) squared template norms (one warp per template).
    double* tsq_d = (double*)((char*)sm + TSQ_OFF);
    if (w < NTPL) {
        const float* tp = tg + w * PIX;
        double a = 0.0;
        for (int p = lane; p < PIX; p += 32) a = fma((double)tp[p], (double)tp[p], a);
        #pragma unroll
        for (int s = 16; s > 0; s >>= 1) a += __shfl_xor_sync(0xffffffffu, a, s);
        if (lane == 0) tsq_d[w] = a;
    }
    __syncthreads();

    uint32_t pmask = 0;                           // per-buffer expected parity bits

    for (int ti = t0; ti < ntiles; ti += G) {
        uint64_t acc[NACC][NGRP];
        #pragma unroll
        for (int k = 0; k < NACC; k++)
            #pragma unroll
            for (int g = 0; g < NGRP; g++) acc[k][g] = 0ull;

        // ---- 4 quarters, NO block syncs between them (buffer q fixed/tile).
        // Warp w owns global chunks c == w (mod 16), increasing; in quarter q
        // (49 == 1 mod 16) its local indices are r0, r0+16, ... with r0=(w-q)&15.
        #pragma unroll
        for (int q = 0; q < NQ; q++) {
            mbar_wait(smb + MB_OFF + (uint32_t)(q * 16), (pmask >> q) & 1u);
            pmask ^= (1u << q);

            const int r0 = (w - q) & 15;
            const int niter = (QCHUNKS - r0 + 15) >> 4;       // 4 if r0==0 else 3
            uint32_t xb = smb + (uint32_t)(q * BUF_BYTES)
                        + (uint32_t)(lane * QROW) + (uint32_t)(r0 * 16);
            uint32_t tb = smb + TM_OFF + (uint32_t)((q * QCHUNKS + r0) * 16);
            #pragma unroll 2
            for (int i = 0; i < niter; i++) {
                uint64_t x01[NGRP], x23[NGRP];
                XLOAD(0, "0"); XLOAD(1, "25088");
                KSTEP(0, "0");     KSTEP(1, "3136");  KSTEP(2, "6272");
                KSTEP(3, "9408");  KSTEP(4, "12544"); KSTEP(5, "15680");
                KSTEP(6, "18816"); KSTEP(7, "21952"); KSTEP(8, "25088");
                KSTEP(9, "28224");
                FMA2(acc[NTPL][0], x01[0], x01[0]); FMA2(acc[NTPL][0], x23[0], x23[0]);
                FMA2(acc[NTPL][1], x01[1], x01[1]); FMA2(acc[NTPL][1], x23[1], x23[1]);
                xb += 256u;                                   // 16 chunks * 16B
                tb += 256u;
            }
        }
        __syncthreads();   // all warps done with all 4 buffers

        // Refill buffers 0,1 for the next tile NOW (covered by the epilogue).
        if (tid == 0 && ti + G < ntiles) {
            asm volatile("fence.proxy.async;" ::: "memory");
            fetch_q(&tmap, ti + G, 0, smb);
            fetch_q(&tmap, ti + G, 1, smb);
        }

        // ---- epilogue in buffers 2,3 (identical arithmetic to R9) ----
        float* red = (float*)((char*)sm + RED_OFF);           // [k][w][img]
        #pragma unroll
        for (int k = 0; k < NACC; k++)
            #pragma unroll
            for (int g = 0; g < NGRP; g++) {
                uint32_t lo, hi;
                asm("mov.b64 {%0, %1}, %2;" : "=r"(lo), "=r"(hi) : "l"(acc[k][g]));
                red[(k * NW + w) * TILE + g * 32 + lane] =
                    __uint_as_float(lo) + __uint_as_float(hi);
            }
        __syncthreads();

        double* xxd = (double*)((char*)sm + XXD_OFF);         // [img]
        float* df = (float*)((char*)sm + DF_OFF);             // [k][img]

        // Pass A: exact 16-way fold of x·x (k=10) via TwoSum -> fp64.
        if (tid < TILE) {
            const float* rp = red + NTPL * (NW * TILE) + tid;
            float fs = 0.f, fe = 0.f;
            #pragma unroll
            for (int ww = 0; ww < NW; ww++) {
                const float v = rp[ww * TILE];
                const float tt = fs + v;
                const float z = tt - fs;
                fe += (fs - (tt - z)) + (v - z);
                fs = tt;
            }
            xxd[tid] = (double)fs + (double)fe;
        }
        __syncthreads();

        // Pass B: fold k=0..9 and form fp32-rounded distances.
        // NTPL*TILE = 640 > THREADS, so grid-stride (2 iterations max).
        for (int p = tid; p < NTPL * TILE; p += THREADS) {
            const int k = p >> 6, img = p & (TILE - 1);
            const float* rp = red + k * (NW * TILE) + img;
            float fs = 0.f, fe = 0.f;
            #pragma unroll
            for (int ww = 0; ww < NW; ww++) {
                const float v = rp[ww * TILE];
                const float tt = fs + v;
                const float z = tt - fs;
                fe += (fs - (tt - z)) + (v - z);
                fs = tt;
            }
            const double c = (double)fs + (double)fe;
            df[p] = (float)((fma(-2.0, c, xxd[img]) + tsq_d[k]) * INV784);
        }
        __syncthreads();

        // argmin (strict <, first index wins ties == jnp.argmin).
        if (tid < TILE) {
            float best = df[tid];
            int bi = 0;
            #pragma unroll
            for (int kk = 1; kk < NTPL; kk++) {
                const float v = df[kk * TILE + tid];
                if (v < best) { best = v; bi = kk; }
            }
            out[(size_t)ti * TILE + tid] = (float)bi;
        }
        __syncthreads();   // scratch (buffers 2,3) dead before refill

        // Refill buffers 2,3 (covered by next tile's quarters 0,1 compute).
        if (tid == 0 && ti + G < ntiles) {
            asm volatile("fence.proxy.async;" ::: "memory");
            fetch_q(&tmap, ti + G, 2, smb);
            fetch_q(&tmap, ti + G, 3, smb);
        }
    }
}

typedef CUresult (*EncodeFn)(CUtensorMap*, CUtensorMapDataType, cuuint32_t, void*,
                             const cuuint64_t*, const cuuint64_t*, const cuuint32_t*,
                             const cuuint32_t*, CUtensorMapInterleave, CUtensorMapSwizzle,
                             CUtensorMapL2promotion, CUtensorMapFloatOOBfill);

extern "C" void kernel_launch(void* const* d_in, const int* in_sizes, int n_in,
                              void* d_out, int out_size) {
    // Robust to input ordering: x is the big one.
    const float* a = (const float*)d_in[0];
    const float* b = (const float*)d_in[1];
    const float* xg;
    const float* tg;
    long nx;
    if (in_sizes[0] >= in_sizes[1]) { xg = a; tg = b; nx = in_sizes[0]; }
    else                            { xg = b; tg = a; nx = in_sizes[1]; }

    const int B = (int)(nx / PIX);
    const int ntiles = B / TILE;   // 262144/64 = 4096, exact

    // Encode the x tensormap: [784 cols x B rows] fp32, box [196 x 64].
    static CUtensorMap tmap;       // persists across graph replays
    {
        EncodeFn enc = nullptr;
        cudaDriverEntryPointQueryResult qr = cudaDriverEntryPointSuccess;
        cudaError_t e = cudaGetDriverEntryPointByVersion(
            "cuTensorMapEncodeTiled", (void**)&enc, 12000, cudaEnableDefault, &qr);
        if (e != cudaSuccess || qr != cudaDriverEntryPointSuccess || enc == nullptr) {
            enc = nullptr;
            cudaGetDriverEntryPoint("cuTensorMapEncodeTiled", (void**)&enc,
                                    cudaEnableDefault, &qr);
        }
        if (enc != nullptr) {
            cuuint64_t gdims[2] = {(cuuint64_t)PIX, (cuuint64_t)B};
            cuuint64_t gstride[1] = {(cuuint64_t)IMG_BYTES};
            cuuint32_t box[2] = {(cuuint32_t)(QCHUNKS * 4), (cuuint32_t)TILE};
            cuuint32_t estride[2] = {1, 1};
            enc(&tmap, CU_TENSOR_MAP_DATA_TYPE_FLOAT32, 2, (void*)xg,
                gdims, gstride, box, estride,
                CU_TENSOR_MAP_INTERLEAVE_NONE, CU_TENSOR_MAP_SWIZZLE_NONE,
                CU_TENSOR_MAP_L2_PROMOTION_L2_128B, CU_TENSOR_MAP_FLOAT_OOB_FILL_NONE);
        }
    }

    int dev = 0;
    cudaGetDevice(&dev);
    int nsm = 148;
    cudaDeviceGetAttribute(&nsm, cudaDevAttrMultiProcessorCount, dev);
    int grid = nsm < ntiles ? nsm : ntiles;

    cudaFuncSetAttribute(mse_argmin_kernel,
                         cudaFuncAttributeMaxDynamicSharedMemorySize, SMEM_TOTAL);

    mse_argmin_kernel<<<grid, THREADS, SMEM_TOTAL>>>(tmap, tg, (float*)d_out, ntiles);
}